// round 7
// baseline (speedup 1.0000x reference)
#include <cuda_runtime.h>
#include <cstdint>

// ---------------------------------------------------------------------------
// FloodGNN: 2-layer GraphSAGE + linear head, transform-then-aggregate.
// R7: layer-2 = single fused kernel (per-128-row tile: gather h1 into smem,
// then FFMA2 GEMM from smem). Gathers reverted to unroll x4 (occupancy).
// Stream fork keeps CSR build off the critical path.
// ---------------------------------------------------------------------------

constexpr int N_NODES = 100000;
constexpr int E_EDGES = 1600000;
constexpr int IN_DIM  = 128;
constexpr int HID     = 64;
constexpr int STRIDE  = 96;   // neighbor bucket capacity (mean deg = 16)

__device__ int   g_cnt[N_NODES];
__device__ int   g_csr[(size_t)N_NODES * STRIDE];
__device__ float g_y [(size_t)N_NODES * HID];   // layer-1: x @ W1_l
__device__ float g_z [(size_t)N_NODES * HID];   // layer-1: x @ W1_r + b1
__device__ float g_y2[(size_t)N_NODES * HID];   // layer-2: h1 @ W2_l
__device__ float g_z2[(size_t)N_NODES * HID];   // layer-2: h1 @ W2_r + b2

// ---------------------------------------------------------------------------
__global__ void k_zero_cnt() {
    int i = blockIdx.x * blockDim.x + threadIdx.x;
    if (i < N_NODES / 4)
        reinterpret_cast<int4*>(g_cnt)[i] = make_int4(0, 0, 0, 0);
}

__global__ void k_build(const int* __restrict__ ei) {
    int i = blockIdx.x * blockDim.x + threadIdx.x;
    if (i >= E_EDGES / 4) return;
    int4 s = __ldg(reinterpret_cast<const int4*>(ei) + i);
    int4 d = __ldg(reinterpret_cast<const int4*>(ei + E_EDGES) + i);
    int slot;
    slot = atomicAdd(&g_cnt[d.x], 1); if (slot < STRIDE) g_csr[(size_t)d.x * STRIDE + slot] = s.x;
    slot = atomicAdd(&g_cnt[d.y], 1); if (slot < STRIDE) g_csr[(size_t)d.y * STRIDE + slot] = s.y;
    slot = atomicAdd(&g_cnt[d.z], 1); if (slot < STRIDE) g_csr[(size_t)d.z * STRIDE + slot] = s.z;
    slot = atomicAdd(&g_cnt[d.w], 1); if (slot < STRIDE) g_csr[(size_t)d.w * STRIDE + slot] = s.w;
}

// ---------------------------------------------------------------------------
__device__ __forceinline__ unsigned long long ffma2(
    unsigned long long a, unsigned long long b, unsigned long long c)
{
    unsigned long long d;
    asm("fma.rn.f32x2 %0, %1, %2, %3;" : "=l"(d) : "l"(a), "l"(b), "l"(c));
    return d;
}

// Sum of 4 neighbor float4 slices of g_y (helper for gather loops).
__device__ __forceinline__ void acc4(float4& acc, int4 i0, int part,
                                     const float* __restrict__ ybuf)
{
    float4 v0 = *reinterpret_cast<const float4*>(&ybuf[(size_t)i0.x * HID + part * 4]);
    float4 v1 = *reinterpret_cast<const float4*>(&ybuf[(size_t)i0.y * HID + part * 4]);
    float4 v2 = *reinterpret_cast<const float4*>(&ybuf[(size_t)i0.z * HID + part * 4]);
    float4 v3 = *reinterpret_cast<const float4*>(&ybuf[(size_t)i0.w * HID + part * 4]);
    acc.x += (v0.x + v1.x) + (v2.x + v3.x);
    acc.y += (v0.y + v1.y) + (v2.y + v3.y);
    acc.z += (v0.z + v1.z) + (v2.z + v3.z);
    acc.w += (v0.w + v1.w) + (v2.w + v3.w);
}

// ---------------------------------------------------------------------------
// Layer-1 GEMM: per 128-row block, g_y = x@W1l, g_z = x@W1r + b1.
// Thread (tx,ty) computes an 8x8 micro-tile as 32 packed f32x2 accumulators.
// ---------------------------------------------------------------------------
__global__ void __launch_bounds__(256, 2) k_gemm1(
    const float* __restrict__ xin,
    const float* __restrict__ Wl,
    const float* __restrict__ Wr,
    const float* __restrict__ bias)
{
    constexpr int K = IN_DIM;
    constexpr int KB = 16;
    constexpr int NSLAB = K / KB;
    __shared__ float2 xs[128][KB + 2];
    __shared__ float  ws[KB][128];

    const int tid = threadIdx.x;
    const int tx = tid & 15;
    const int ty = tid >> 4;
    const int row0 = blockIdx.x * 128;

    unsigned long long acc[8][4];
    #pragma unroll
    for (int r = 0; r < 8; r++)
        #pragma unroll
        for (int c = 0; c < 4; c++) acc[r][c] = 0ULL;

    for (int slab = 0; slab < NSLAB; slab++) {
        const int k0 = slab * KB;
        __syncthreads();
        #pragma unroll
        for (int i = 0; i < 2; i++) {
            int v  = tid + i * 256;
            int kk = v >> 5;
            int cs = v & 31;
            int gk = k0 + kk;
            float4 w;
            if (cs < 16) w = *reinterpret_cast<const float4*>(&Wl[gk * HID + cs * 4]);
            else         w = *reinterpret_cast<const float4*>(&Wr[gk * HID + (cs - 16) * 4]);
            *reinterpret_cast<float4*>(&ws[kk][cs * 4]) = w;
        }
        #pragma unroll
        for (int i = 0; i < 2; i++) {
            int v   = tid + i * 256;
            int row = v >> 2;
            int kq  = v & 3;
            int grow = row0 + row;
            float4 xv = make_float4(0.f, 0.f, 0.f, 0.f);
            if (grow < N_NODES)
                xv = *reinterpret_cast<const float4*>(&xin[(size_t)grow * K + k0 + kq * 4]);
            xs[row][kq * 4 + 0] = make_float2(xv.x, xv.x);
            xs[row][kq * 4 + 1] = make_float2(xv.y, xv.y);
            xs[row][kq * 4 + 2] = make_float2(xv.z, xv.z);
            xs[row][kq * 4 + 3] = make_float2(xv.w, xv.w);
        }
        __syncthreads();

        #pragma unroll
        for (int kk = 0; kk < KB; kk += 2) {
            ulonglong2 w0a = *reinterpret_cast<const ulonglong2*>(&ws[kk][tx * 8]);
            ulonglong2 w0b = *reinterpret_cast<const ulonglong2*>(&ws[kk][tx * 8 + 4]);
            ulonglong2 w1a = *reinterpret_cast<const ulonglong2*>(&ws[kk + 1][tx * 8]);
            ulonglong2 w1b = *reinterpret_cast<const ulonglong2*>(&ws[kk + 1][tx * 8 + 4]);
            #pragma unroll
            for (int r = 0; r < 8; r++) {
                ulonglong2 a = *reinterpret_cast<const ulonglong2*>(&xs[ty * 8 + r][kk]);
                acc[r][0] = ffma2(a.x, w0a.x, acc[r][0]);
                acc[r][1] = ffma2(a.x, w0a.y, acc[r][1]);
                acc[r][2] = ffma2(a.x, w0b.x, acc[r][2]);
                acc[r][3] = ffma2(a.x, w0b.y, acc[r][3]);
                acc[r][0] = ffma2(a.y, w1a.x, acc[r][0]);
                acc[r][1] = ffma2(a.y, w1a.y, acc[r][1]);
                acc[r][2] = ffma2(a.y, w1b.x, acc[r][2]);
                acc[r][3] = ffma2(a.y, w1b.y, acc[r][3]);
            }
        }
    }

    float bb[8] = {0.f};
    if (tx >= 8) {
        int cb = tx * 8 - 64;
        float4 q0 = *reinterpret_cast<const float4*>(&bias[cb]);
        float4 q1 = *reinterpret_cast<const float4*>(&bias[cb + 4]);
        bb[0] = q0.x; bb[1] = q0.y; bb[2] = q0.z; bb[3] = q0.w;
        bb[4] = q1.x; bb[5] = q1.y; bb[6] = q1.z; bb[7] = q1.w;
    }
    #pragma unroll
    for (int r = 0; r < 8; r++) {
        int grow = row0 + ty * 8 + r;
        if (grow >= N_NODES) break;
        float2 c0 = *reinterpret_cast<float2*>(&acc[r][0]);
        float2 c1 = *reinterpret_cast<float2*>(&acc[r][1]);
        float2 c2 = *reinterpret_cast<float2*>(&acc[r][2]);
        float2 c3 = *reinterpret_cast<float2*>(&acc[r][3]);
        if (tx < 8) {
            size_t base = (size_t)grow * HID + tx * 8;
            *reinterpret_cast<float4*>(&g_y[base])     = make_float4(c0.x, c0.y, c1.x, c1.y);
            *reinterpret_cast<float4*>(&g_y[base + 4]) = make_float4(c2.x, c2.y, c3.x, c3.y);
        } else {
            size_t base = (size_t)grow * HID + (tx * 8 - 64);
            *reinterpret_cast<float4*>(&g_z[base]) =
                make_float4(c0.x + bb[0], c0.y + bb[1], c1.x + bb[2], c1.y + bb[3]);
            *reinterpret_cast<float4*>(&g_z[base + 4]) =
                make_float4(c2.x + bb[4], c2.y + bb[5], c3.x + bb[6], c3.y + bb[7]);
        }
    }
}

// ---------------------------------------------------------------------------
// Fused layer-2: per 128-row block.
// Phase A: gather h1[row] = relu(mean(y1[neigh])*inv + z1[row]) straight into
//          the smem x-tile (duplicated (v,v) float2 pairs).
// Phase B: FFMA2 GEMM from smem: g_y2 = h1@W2l, g_z2 = h1@W2r + b2.
// Dynamic smem: xs 128x66 float2 (67,584 B) + ws 64x128 float (32,768 B).
// ---------------------------------------------------------------------------
constexpr int XS_STRIDE = HID + 2;   // float2 elements per row (pad 2)
constexpr int SMEM_GG = 128 * XS_STRIDE * (int)sizeof(float2) + HID * 128 * (int)sizeof(float);

__global__ void __launch_bounds__(256, 2) k_gather_gemm(
    const float* __restrict__ Wl,
    const float* __restrict__ Wr,
    const float* __restrict__ bias)
{
    extern __shared__ float smem[];
    float2* xs = reinterpret_cast<float2*>(smem);           // [128][XS_STRIDE]
    float*  ws = smem + 128 * XS_STRIDE * 2;                // [HID][128]

    const int tid = threadIdx.x;
    const int tx = tid & 15;
    const int ty = tid >> 4;
    const int row0 = blockIdx.x * 128;

    // ---- stage full W tile: 64 k-rows x 128 cols = 2048 float4 ----
    #pragma unroll
    for (int i = 0; i < 8; i++) {
        int v  = tid + i * 256;          // [0,2048)
        int kk = v >> 5;
        int cs = v & 31;
        float4 w;
        if (cs < 16) w = *reinterpret_cast<const float4*>(&Wl[kk * HID + cs * 4]);
        else         w = *reinterpret_cast<const float4*>(&Wr[kk * HID + (cs - 16) * 4]);
        *reinterpret_cast<float4*>(&ws[kk * 128 + cs * 4]) = w;
    }

    // ---- phase A: gather h1 for the block's 128 rows into xs ----
    #pragma unroll
    for (int i = 0; i < 8; i++) {
        int task = tid + i * 256;        // [0,2048): (row, part)
        int row  = task >> 4;
        int part = task & 15;
        int dst  = row0 + row;

        float h0 = 0.f, h1 = 0.f, h2 = 0.f, h3 = 0.f;
        if (dst < N_NODES) {
            int deg = g_cnt[dst];
            int n = deg < STRIDE ? deg : STRIDE;
            const int* lst = &g_csr[(size_t)dst * STRIDE];
            float4 acc = make_float4(0.f, 0.f, 0.f, 0.f);
            int j = 0;
            for (; j + 4 <= n; j += 4)
                acc4(acc, __ldg(reinterpret_cast<const int4*>(lst + j)), part, g_y);
            for (; j < n; j++) {
                int s = __ldg(&lst[j]);
                float4 v = *reinterpret_cast<const float4*>(&g_y[(size_t)s * HID + part * 4]);
                acc.x += v.x; acc.y += v.y; acc.z += v.z; acc.w += v.w;
            }
            float inv = 1.0f / fmaxf((float)deg, 1.0f);
            float4 zv = *reinterpret_cast<const float4*>(&g_z[(size_t)dst * HID + part * 4]);
            h0 = fmaxf(fmaf(acc.x, inv, zv.x), 0.f);
            h1 = fmaxf(fmaf(acc.y, inv, zv.y), 0.f);
            h2 = fmaxf(fmaf(acc.z, inv, zv.z), 0.f);
            h3 = fmaxf(fmaf(acc.w, inv, zv.w), 0.f);
        }
        float2* xr = &xs[row * XS_STRIDE + part * 4];
        xr[0] = make_float2(h0, h0);
        xr[1] = make_float2(h1, h1);
        xr[2] = make_float2(h2, h2);
        xr[3] = make_float2(h3, h3);
    }
    __syncthreads();

    // ---- phase B: GEMM from smem ----
    unsigned long long acc[8][4];
    #pragma unroll
    for (int r = 0; r < 8; r++)
        #pragma unroll
        for (int c = 0; c < 4; c++) acc[r][c] = 0ULL;

    #pragma unroll 8
    for (int kk = 0; kk < HID; kk += 2) {
        ulonglong2 w0a = *reinterpret_cast<const ulonglong2*>(&ws[kk * 128 + tx * 8]);
        ulonglong2 w0b = *reinterpret_cast<const ulonglong2*>(&ws[kk * 128 + tx * 8 + 4]);
        ulonglong2 w1a = *reinterpret_cast<const ulonglong2*>(&ws[(kk + 1) * 128 + tx * 8]);
        ulonglong2 w1b = *reinterpret_cast<const ulonglong2*>(&ws[(kk + 1) * 128 + tx * 8 + 4]);
        #pragma unroll
        for (int r = 0; r < 8; r++) {
            ulonglong2 a = *reinterpret_cast<const ulonglong2*>(
                &xs[(ty * 8 + r) * XS_STRIDE + kk]);
            acc[r][0] = ffma2(a.x, w0a.x, acc[r][0]);
            acc[r][1] = ffma2(a.x, w0a.y, acc[r][1]);
            acc[r][2] = ffma2(a.x, w0b.x, acc[r][2]);
            acc[r][3] = ffma2(a.x, w0b.y, acc[r][3]);
            acc[r][0] = ffma2(a.y, w1a.x, acc[r][0]);
            acc[r][1] = ffma2(a.y, w1a.y, acc[r][1]);
            acc[r][2] = ffma2(a.y, w1b.x, acc[r][2]);
            acc[r][3] = ffma2(a.y, w1b.y, acc[r][3]);
        }
    }

    float bb[8] = {0.f};
    if (tx >= 8) {
        int cb = tx * 8 - 64;
        float4 q0 = *reinterpret_cast<const float4*>(&bias[cb]);
        float4 q1 = *reinterpret_cast<const float4*>(&bias[cb + 4]);
        bb[0] = q0.x; bb[1] = q0.y; bb[2] = q0.z; bb[3] = q0.w;
        bb[4] = q1.x; bb[5] = q1.y; bb[6] = q1.z; bb[7] = q1.w;
    }
    #pragma unroll
    for (int r = 0; r < 8; r++) {
        int grow = row0 + ty * 8 + r;
        if (grow >= N_NODES) break;
        float2 c0 = *reinterpret_cast<float2*>(&acc[r][0]);
        float2 c1 = *reinterpret_cast<float2*>(&acc[r][1]);
        float2 c2 = *reinterpret_cast<float2*>(&acc[r][2]);
        float2 c3 = *reinterpret_cast<float2*>(&acc[r][3]);
        if (tx < 8) {
            size_t base = (size_t)grow * HID + tx * 8;
            *reinterpret_cast<float4*>(&g_y2[base])     = make_float4(c0.x, c0.y, c1.x, c1.y);
            *reinterpret_cast<float4*>(&g_y2[base + 4]) = make_float4(c2.x, c2.y, c3.x, c3.y);
        } else {
            size_t base = (size_t)grow * HID + (tx * 8 - 64);
            *reinterpret_cast<float4*>(&g_z2[base]) =
                make_float4(c0.x + bb[0], c0.y + bb[1], c1.x + bb[2], c1.y + bb[3]);
            *reinterpret_cast<float4*>(&g_z2[base + 4]) =
                make_float4(c2.x + bb[4], c2.y + bb[5], c3.x + bb[6], c3.y + bb[7]);
        }
    }
}

// ---------------------------------------------------------------------------
// Final gather + head: 16 threads per dst row (unroll x4).
//   h2 = relu(mean(y2[neigh])*inv + z2);  out = h2 @ Wc + bc.
// ---------------------------------------------------------------------------
__global__ void __launch_bounds__(256) k_gather_final(
    const float* __restrict__ Wc,
    const float* __restrict__ bc,
    float* __restrict__ out)
{
    int t = blockIdx.x * blockDim.x + threadIdx.x;
    int dst = t >> 4;
    int part = t & 15;
    if (dst >= N_NODES) return;

    int deg = g_cnt[dst];
    int n = deg < STRIDE ? deg : STRIDE;
    const int* lst = &g_csr[(size_t)dst * STRIDE];

    float4 acc = make_float4(0.f, 0.f, 0.f, 0.f);
    int j = 0;
    for (; j + 4 <= n; j += 4)
        acc4(acc, __ldg(reinterpret_cast<const int4*>(lst + j)), part, g_y2);
    for (; j < n; j++) {
        int s = __ldg(&lst[j]);
        float4 v = *reinterpret_cast<const float4*>(&g_y2[(size_t)s * HID + part * 4]);
        acc.x += v.x; acc.y += v.y; acc.z += v.z; acc.w += v.w;
    }

    float inv = 1.0f / fmaxf((float)deg, 1.0f);
    float4 zv = *reinterpret_cast<const float4*>(&g_z2[(size_t)dst * HID + part * 4]);
    float h0 = fmaxf(fmaf(acc.x, inv, zv.x), 0.f);
    float h1 = fmaxf(fmaf(acc.y, inv, zv.y), 0.f);
    float h2 = fmaxf(fmaf(acc.z, inv, zv.z), 0.f);
    float h3 = fmaxf(fmaf(acc.w, inv, zv.w), 0.f);

    float4 wc = *reinterpret_cast<const float4*>(&Wc[part * 4]);
    float s = h0 * wc.x + h1 * wc.y + h2 * wc.z + h3 * wc.w;
    #pragma unroll
    for (int o = 8; o > 0; o >>= 1)
        s += __shfl_down_sync(0xffffffffu, s, o, 16);
    if (part == 0) out[dst] = s + __ldg(&bc[0]);
}

// ---------------------------------------------------------------------------
extern "C" void kernel_launch(void* const* d_in, const int* in_sizes, int n_in,
                              void* d_out, int out_size)
{
    const float* x   = (const float*)d_in[0];
    const int*   ei  = (const int*)  d_in[1];
    const float* W1l = (const float*)d_in[2];
    const float* W1r = (const float*)d_in[3];
    const float* b1  = (const float*)d_in[4];
    const float* W2l = (const float*)d_in[5];
    const float* W2r = (const float*)d_in[6];
    const float* b2  = (const float*)d_in[7];
    const float* Wc  = (const float*)d_in[8];
    const float* bc  = (const float*)d_in[9];
    float* out = (float*)d_out;

    cudaFuncSetAttribute(k_gather_gemm,
                         cudaFuncAttributeMaxDynamicSharedMemorySize, SMEM_GG);

    constexpr int ZC_BLKS    = (N_NODES / 4 + 255) / 256;                  // 98
    constexpr int BUILD_BLKS = (E_EDGES / 4 + 255) / 256;                  // 1563
    constexpr int GEMM_BLKS  = (N_NODES + 127) / 128;                      // 782
    constexpr int GATH_BLKS  = (int)(((size_t)N_NODES * 16 + 255) / 256);  // 6250

    // Fork: [zero_cnt -> build] overlaps gemm1 (independent pipes).
    cudaStream_t s2;
    cudaEvent_t evFork, evJoin;
    cudaStreamCreateWithFlags(&s2, cudaStreamNonBlocking);
    cudaEventCreateWithFlags(&evFork, cudaEventDisableTiming);
    cudaEventCreateWithFlags(&evJoin, cudaEventDisableTiming);

    cudaEventRecord(evFork, 0);
    cudaStreamWaitEvent(s2, evFork, 0);
    k_zero_cnt<<<ZC_BLKS, 256, 0, s2>>>();
    k_build<<<BUILD_BLKS, 256, 0, s2>>>(ei);
    cudaEventRecord(evJoin, s2);

    k_gemm1<<<GEMM_BLKS, 256>>>(x, W1l, W1r, b1);

    cudaStreamWaitEvent(0, evJoin, 0);
    k_gather_gemm<<<GEMM_BLKS, 256, SMEM_GG>>>(W2l, W2r, b2);
    k_gather_final<<<GATH_BLKS, 256>>>(Wc, bc, out);

    cudaEventDestroy(evFork);
    cudaEventDestroy(evJoin);
    cudaStreamDestroy(s2);
}

// round 8
// speedup vs baseline: 1.1377x; 1.1377x over previous
#include <cuda_runtime.h>
#include <cstdint>

// ---------------------------------------------------------------------------
// FloodGNN: 2-layer GraphSAGE + linear head, transform-then-aggregate.
// R8: revert R7's monolithic fusion (occupancy-killed). R5 skeleton +
// validated deltas only: stream-fork (build overlaps gemm1), gathers at
// unroll x4 / 84% occ, relu fused into gather<0> so both GEMMs are identical.
// ---------------------------------------------------------------------------

constexpr int N_NODES = 100000;
constexpr int E_EDGES = 1600000;
constexpr int IN_DIM  = 128;
constexpr int HID     = 64;
constexpr int STRIDE  = 96;   // neighbor bucket capacity (mean deg = 16)

__device__ int   g_cnt[N_NODES];
__device__ int   g_csr[(size_t)N_NODES * STRIDE];
__device__ float g_y [(size_t)N_NODES * HID];   // current layer: feat @ W_l
__device__ float g_z [(size_t)N_NODES * HID];   // current layer: feat @ W_r + b
__device__ float g_h [(size_t)N_NODES * HID];   // gathered layer-2 input
__device__ float g_y2[(size_t)N_NODES * HID];   // layer-2: h1 @ W2_l
__device__ float g_z2[(size_t)N_NODES * HID];   // layer-2: h1 @ W2_r + b2

// ---------------------------------------------------------------------------
__global__ void k_zero_cnt() {
    int i = blockIdx.x * blockDim.x + threadIdx.x;
    if (i < N_NODES / 4)
        reinterpret_cast<int4*>(g_cnt)[i] = make_int4(0, 0, 0, 0);
}

__global__ void k_build(const int* __restrict__ ei) {
    int i = blockIdx.x * blockDim.x + threadIdx.x;
    if (i >= E_EDGES / 4) return;
    int4 s = __ldg(reinterpret_cast<const int4*>(ei) + i);
    int4 d = __ldg(reinterpret_cast<const int4*>(ei + E_EDGES) + i);
    int slot;
    slot = atomicAdd(&g_cnt[d.x], 1); if (slot < STRIDE) g_csr[(size_t)d.x * STRIDE + slot] = s.x;
    slot = atomicAdd(&g_cnt[d.y], 1); if (slot < STRIDE) g_csr[(size_t)d.y * STRIDE + slot] = s.y;
    slot = atomicAdd(&g_cnt[d.z], 1); if (slot < STRIDE) g_csr[(size_t)d.z * STRIDE + slot] = s.z;
    slot = atomicAdd(&g_cnt[d.w], 1); if (slot < STRIDE) g_csr[(size_t)d.w * STRIDE + slot] = s.w;
}

// ---------------------------------------------------------------------------
__device__ __forceinline__ unsigned long long ffma2(
    unsigned long long a, unsigned long long b, unsigned long long c)
{
    unsigned long long d;
    asm("fma.rn.f32x2 %0, %1, %2, %3;" : "=l"(d) : "l"(a), "l"(b), "l"(c));
    return d;
}

// Sum 4 neighbor float4 slices of ybuf into acc.
__device__ __forceinline__ void acc4(float4& acc, int4 i0, int part,
                                     const float* __restrict__ ybuf)
{
    float4 v0 = *reinterpret_cast<const float4*>(&ybuf[(size_t)i0.x * HID + part * 4]);
    float4 v1 = *reinterpret_cast<const float4*>(&ybuf[(size_t)i0.y * HID + part * 4]);
    float4 v2 = *reinterpret_cast<const float4*>(&ybuf[(size_t)i0.z * HID + part * 4]);
    float4 v3 = *reinterpret_cast<const float4*>(&ybuf[(size_t)i0.w * HID + part * 4]);
    acc.x += (v0.x + v1.x) + (v2.x + v3.x);
    acc.y += (v0.y + v1.y) + (v2.y + v3.y);
    acc.z += (v0.z + v1.z) + (v2.z + v3.z);
    acc.w += (v0.w + v1.w) + (v2.w + v3.w);
}

// ---------------------------------------------------------------------------
// GEMM transform: per 128-row block,
//   yout[row] = xin[row] @ Wl ;  zout[row] = xin[row] @ Wr + bias
// Thread (tx,ty) computes an 8x8 micro-tile as 32 packed f32x2 accumulators.
// ---------------------------------------------------------------------------
template <int K>
__global__ void __launch_bounds__(256, 2) k_gemm(
    const float* __restrict__ xin,
    const float* __restrict__ Wl,
    const float* __restrict__ Wr,
    const float* __restrict__ bias,
    float* __restrict__ yout,
    float* __restrict__ zout)
{
    constexpr int KB = 16;
    constexpr int NSLAB = K / KB;
    __shared__ float2 xs[128][KB + 2];
    __shared__ float  ws[KB][128];

    const int tid = threadIdx.x;
    const int tx = tid & 15;
    const int ty = tid >> 4;
    const int row0 = blockIdx.x * 128;

    unsigned long long acc[8][4];
    #pragma unroll
    for (int r = 0; r < 8; r++)
        #pragma unroll
        for (int c = 0; c < 4; c++) acc[r][c] = 0ULL;

    for (int slab = 0; slab < NSLAB; slab++) {
        const int k0 = slab * KB;
        __syncthreads();
        #pragma unroll
        for (int i = 0; i < 2; i++) {
            int v  = tid + i * 256;
            int kk = v >> 5;
            int cs = v & 31;
            int gk = k0 + kk;
            float4 w;
            if (cs < 16) w = *reinterpret_cast<const float4*>(&Wl[gk * HID + cs * 4]);
            else         w = *reinterpret_cast<const float4*>(&Wr[gk * HID + (cs - 16) * 4]);
            *reinterpret_cast<float4*>(&ws[kk][cs * 4]) = w;
        }
        #pragma unroll
        for (int i = 0; i < 2; i++) {
            int v   = tid + i * 256;
            int row = v >> 2;
            int kq  = v & 3;
            int grow = row0 + row;
            float4 xv = make_float4(0.f, 0.f, 0.f, 0.f);
            if (grow < N_NODES)
                xv = *reinterpret_cast<const float4*>(&xin[(size_t)grow * K + k0 + kq * 4]);
            xs[row][kq * 4 + 0] = make_float2(xv.x, xv.x);
            xs[row][kq * 4 + 1] = make_float2(xv.y, xv.y);
            xs[row][kq * 4 + 2] = make_float2(xv.z, xv.z);
            xs[row][kq * 4 + 3] = make_float2(xv.w, xv.w);
        }
        __syncthreads();

        #pragma unroll
        for (int kk = 0; kk < KB; kk += 2) {
            ulonglong2 w0a = *reinterpret_cast<const ulonglong2*>(&ws[kk][tx * 8]);
            ulonglong2 w0b = *reinterpret_cast<const ulonglong2*>(&ws[kk][tx * 8 + 4]);
            ulonglong2 w1a = *reinterpret_cast<const ulonglong2*>(&ws[kk + 1][tx * 8]);
            ulonglong2 w1b = *reinterpret_cast<const ulonglong2*>(&ws[kk + 1][tx * 8 + 4]);
            #pragma unroll
            for (int r = 0; r < 8; r++) {
                ulonglong2 a = *reinterpret_cast<const ulonglong2*>(&xs[ty * 8 + r][kk]);
                acc[r][0] = ffma2(a.x, w0a.x, acc[r][0]);
                acc[r][1] = ffma2(a.x, w0a.y, acc[r][1]);
                acc[r][2] = ffma2(a.x, w0b.x, acc[r][2]);
                acc[r][3] = ffma2(a.x, w0b.y, acc[r][3]);
                acc[r][0] = ffma2(a.y, w1a.x, acc[r][0]);
                acc[r][1] = ffma2(a.y, w1a.y, acc[r][1]);
                acc[r][2] = ffma2(a.y, w1b.x, acc[r][2]);
                acc[r][3] = ffma2(a.y, w1b.y, acc[r][3]);
            }
        }
    }

    float bb[8] = {0.f};
    if (tx >= 8) {
        int cb = tx * 8 - 64;
        float4 q0 = *reinterpret_cast<const float4*>(&bias[cb]);
        float4 q1 = *reinterpret_cast<const float4*>(&bias[cb + 4]);
        bb[0] = q0.x; bb[1] = q0.y; bb[2] = q0.z; bb[3] = q0.w;
        bb[4] = q1.x; bb[5] = q1.y; bb[6] = q1.z; bb[7] = q1.w;
    }
    #pragma unroll
    for (int r = 0; r < 8; r++) {
        int grow = row0 + ty * 8 + r;
        if (grow >= N_NODES) break;
        float2 c0 = *reinterpret_cast<float2*>(&acc[r][0]);
        float2 c1 = *reinterpret_cast<float2*>(&acc[r][1]);
        float2 c2 = *reinterpret_cast<float2*>(&acc[r][2]);
        float2 c3 = *reinterpret_cast<float2*>(&acc[r][3]);
        if (tx < 8) {
            size_t base = (size_t)grow * HID + tx * 8;
            *reinterpret_cast<float4*>(&yout[base])     = make_float4(c0.x, c0.y, c1.x, c1.y);
            *reinterpret_cast<float4*>(&yout[base + 4]) = make_float4(c2.x, c2.y, c3.x, c3.y);
        } else {
            size_t base = (size_t)grow * HID + (tx * 8 - 64);
            *reinterpret_cast<float4*>(&zout[base]) =
                make_float4(c0.x + bb[0], c0.y + bb[1], c1.x + bb[2], c1.y + bb[3]);
            *reinterpret_cast<float4*>(&zout[base + 4]) =
                make_float4(c2.x + bb[4], c2.y + bb[5], c3.x + bb[6], c3.y + bb[7]);
        }
    }
}

// ---------------------------------------------------------------------------
// CSR gather: 16 threads per dst row; thread owns one float4 slice (unroll x4).
// acc = sum over neighbors of ybuf[src]; h = relu(acc*inv + zbuf[dst]).
//   FINAL=false: g_h[dst] = h                     (layer-2 input)
//   FINAL=true : out[dst] = h @ Wc + bc           (fused head)
// ---------------------------------------------------------------------------
template <bool FINAL>
__global__ void __launch_bounds__(256) k_gather(
    const float* __restrict__ ybuf,
    const float* __restrict__ zbuf,
    const float* __restrict__ Wc,
    const float* __restrict__ bc,
    float* __restrict__ out)
{
    int t = blockIdx.x * blockDim.x + threadIdx.x;
    int dst = t >> 4;
    int part = t & 15;
    if (dst >= N_NODES) return;

    int deg = g_cnt[dst];
    int n = deg < STRIDE ? deg : STRIDE;
    const int* lst = &g_csr[(size_t)dst * STRIDE];

    float4 acc = make_float4(0.f, 0.f, 0.f, 0.f);
    int j = 0;
    for (; j + 4 <= n; j += 4)
        acc4(acc, __ldg(reinterpret_cast<const int4*>(lst + j)), part, ybuf);
    for (; j < n; j++) {
        int s = __ldg(&lst[j]);
        float4 v = *reinterpret_cast<const float4*>(&ybuf[(size_t)s * HID + part * 4]);
        acc.x += v.x; acc.y += v.y; acc.z += v.z; acc.w += v.w;
    }

    float inv = 1.0f / fmaxf((float)deg, 1.0f);
    float4 zv = *reinterpret_cast<const float4*>(&zbuf[(size_t)dst * HID + part * 4]);
    float h0 = fmaxf(fmaf(acc.x, inv, zv.x), 0.f);
    float h1 = fmaxf(fmaf(acc.y, inv, zv.y), 0.f);
    float h2 = fmaxf(fmaf(acc.z, inv, zv.z), 0.f);
    float h3 = fmaxf(fmaf(acc.w, inv, zv.w), 0.f);

    if (!FINAL) {
        *reinterpret_cast<float4*>(&g_h[(size_t)dst * HID + part * 4]) =
            make_float4(h0, h1, h2, h3);
    } else {
        float4 wc = *reinterpret_cast<const float4*>(&Wc[part * 4]);
        float s = h0 * wc.x + h1 * wc.y + h2 * wc.z + h3 * wc.w;
        #pragma unroll
        for (int o = 8; o > 0; o >>= 1)
            s += __shfl_down_sync(0xffffffffu, s, o, 16);
        if (part == 0) out[dst] = s + __ldg(&bc[0]);
    }
}

// ---------------------------------------------------------------------------
extern "C" void kernel_launch(void* const* d_in, const int* in_sizes, int n_in,
                              void* d_out, int out_size)
{
    const float* x   = (const float*)d_in[0];
    const int*   ei  = (const int*)  d_in[1];
    const float* W1l = (const float*)d_in[2];
    const float* W1r = (const float*)d_in[3];
    const float* b1  = (const float*)d_in[4];
    const float* W2l = (const float*)d_in[5];
    const float* W2r = (const float*)d_in[6];
    const float* b2  = (const float*)d_in[7];
    const float* Wc  = (const float*)d_in[8];
    const float* bc  = (const float*)d_in[9];
    float* out = (float*)d_out;

    void *py = nullptr, *pz = nullptr, *ph = nullptr, *py2 = nullptr, *pz2 = nullptr;
    cudaGetSymbolAddress(&py,  g_y);
    cudaGetSymbolAddress(&pz,  g_z);
    cudaGetSymbolAddress(&ph,  g_h);
    cudaGetSymbolAddress(&py2, g_y2);
    cudaGetSymbolAddress(&pz2, g_z2);

    constexpr int ZC_BLKS    = (N_NODES / 4 + 255) / 256;                  // 98
    constexpr int BUILD_BLKS = (E_EDGES / 4 + 255) / 256;                  // 1563
    constexpr int GEMM_BLKS  = (N_NODES + 127) / 128;                      // 782
    constexpr int GATH_BLKS  = (int)(((size_t)N_NODES * 16 + 255) / 256);  // 6250

    // Fork: [zero_cnt -> build] overlaps gemm1 (independent pipes).
    cudaStream_t s2;
    cudaEvent_t evFork, evJoin;
    cudaStreamCreateWithFlags(&s2, cudaStreamNonBlocking);
    cudaEventCreateWithFlags(&evFork, cudaEventDisableTiming);
    cudaEventCreateWithFlags(&evJoin, cudaEventDisableTiming);

    cudaEventRecord(evFork, 0);
    cudaStreamWaitEvent(s2, evFork, 0);
    k_zero_cnt<<<ZC_BLKS, 256, 0, s2>>>();
    k_build<<<BUILD_BLKS, 256, 0, s2>>>(ei);
    cudaEventRecord(evJoin, s2);

    k_gemm<IN_DIM><<<GEMM_BLKS, 256>>>(x, W1l, W1r, b1, (float*)py, (float*)pz);

    cudaStreamWaitEvent(0, evJoin, 0);
    k_gather<false><<<GATH_BLKS, 256>>>((const float*)py, (const float*)pz,
                                        nullptr, nullptr, nullptr);
    k_gemm<HID><<<GEMM_BLKS, 256>>>((const float*)ph, W2l, W2r, b2,
                                    (float*)py2, (float*)pz2);
    k_gather<true><<<GATH_BLKS, 256>>>((const float*)py2, (const float*)pz2,
                                       Wc, bc, out);

    cudaEventDestroy(evFork);
    cudaEventDestroy(evJoin);
    cudaStreamDestroy(s2);
}

// round 9
// speedup vs baseline: 1.2206x; 1.0728x over previous
#include <cuda_runtime.h>
#include <cuda_fp16.h>
#include <cstdint>

// ---------------------------------------------------------------------------
// FloodGNN: 2-layer GraphSAGE + linear head, transform-then-aggregate.
// R9: message features (y = feat @ W_l) stored as fp16 -> gather edge traffic
// halves (256B -> 128B per edge). All accumulation stays fp32; z/h fp32.
// Keeps R8 skeleton: stream-fork build, unroll-x4 gathers, FFMA2 GEMMs.
// ---------------------------------------------------------------------------

constexpr int N_NODES = 100000;
constexpr int E_EDGES = 1600000;
constexpr int IN_DIM  = 128;
constexpr int HID     = 64;
constexpr int STRIDE  = 96;   // neighbor bucket capacity (mean deg = 16)

__device__ int    g_cnt[N_NODES];
__device__ int    g_csr[(size_t)N_NODES * STRIDE];
__device__ __half g_y [(size_t)N_NODES * HID];   // layer-1 messages (fp16)
__device__ float  g_z [(size_t)N_NODES * HID];   // layer-1 self (fp32)
__device__ float  g_h [(size_t)N_NODES * HID];   // layer-2 input (fp32)
__device__ __half g_y2[(size_t)N_NODES * HID];   // layer-2 messages (fp16)
__device__ float  g_z2[(size_t)N_NODES * HID];   // layer-2 self (fp32)

// ---------------------------------------------------------------------------
__global__ void k_zero_cnt() {
    int i = blockIdx.x * blockDim.x + threadIdx.x;
    if (i < N_NODES / 4)
        reinterpret_cast<int4*>(g_cnt)[i] = make_int4(0, 0, 0, 0);
}

__global__ void k_build(const int* __restrict__ ei) {
    int i = blockIdx.x * blockDim.x + threadIdx.x;
    if (i >= E_EDGES / 4) return;
    int4 s = __ldg(reinterpret_cast<const int4*>(ei) + i);
    int4 d = __ldg(reinterpret_cast<const int4*>(ei + E_EDGES) + i);
    int slot;
    slot = atomicAdd(&g_cnt[d.x], 1); if (slot < STRIDE) g_csr[(size_t)d.x * STRIDE + slot] = s.x;
    slot = atomicAdd(&g_cnt[d.y], 1); if (slot < STRIDE) g_csr[(size_t)d.y * STRIDE + slot] = s.y;
    slot = atomicAdd(&g_cnt[d.z], 1); if (slot < STRIDE) g_csr[(size_t)d.z * STRIDE + slot] = s.z;
    slot = atomicAdd(&g_cnt[d.w], 1); if (slot < STRIDE) g_csr[(size_t)d.w * STRIDE + slot] = s.w;
}

// ---------------------------------------------------------------------------
__device__ __forceinline__ unsigned long long ffma2(
    unsigned long long a, unsigned long long b, unsigned long long c)
{
    unsigned long long d;
    asm("fma.rn.f32x2 %0, %1, %2, %3;" : "=l"(d) : "l"(a), "l"(b), "l"(c));
    return d;
}

// Accumulate one neighbor's 8 fp16 message cols into 4 fp32 float2 accs.
__device__ __forceinline__ void accN(float2 acc[4], int src, int part,
                                     const __half* __restrict__ ybuf)
{
    uint4 a = __ldg(reinterpret_cast<const uint4*>(&ybuf[(size_t)src * HID + part * 8]));
    const __half2* ah = reinterpret_cast<const __half2*>(&a);
    #pragma unroll
    for (int q = 0; q < 4; q++) {
        float2 f = __half22float2(ah[q]);
        acc[q].x += f.x;
        acc[q].y += f.y;
    }
}

// ---------------------------------------------------------------------------
// GEMM transform: per 128-row block,
//   yout[row] = xin[row] @ Wl   (stored fp16)
//   zout[row] = xin[row] @ Wr + bias   (fp32)
// Thread (tx,ty) computes an 8x8 micro-tile as 32 packed f32x2 accumulators.
// ---------------------------------------------------------------------------
template <int K>
__global__ void __launch_bounds__(256, 2) k_gemm(
    const float* __restrict__ xin,
    const float* __restrict__ Wl,
    const float* __restrict__ Wr,
    const float* __restrict__ bias,
    __half* __restrict__ yout,
    float* __restrict__ zout)
{
    constexpr int KB = 16;
    constexpr int NSLAB = K / KB;
    __shared__ float2 xs[128][KB + 2];
    __shared__ float  ws[KB][128];

    const int tid = threadIdx.x;
    const int tx = tid & 15;
    const int ty = tid >> 4;
    const int row0 = blockIdx.x * 128;

    unsigned long long acc[8][4];
    #pragma unroll
    for (int r = 0; r < 8; r++)
        #pragma unroll
        for (int c = 0; c < 4; c++) acc[r][c] = 0ULL;

    for (int slab = 0; slab < NSLAB; slab++) {
        const int k0 = slab * KB;
        __syncthreads();
        #pragma unroll
        for (int i = 0; i < 2; i++) {
            int v  = tid + i * 256;
            int kk = v >> 5;
            int cs = v & 31;
            int gk = k0 + kk;
            float4 w;
            if (cs < 16) w = *reinterpret_cast<const float4*>(&Wl[gk * HID + cs * 4]);
            else         w = *reinterpret_cast<const float4*>(&Wr[gk * HID + (cs - 16) * 4]);
            *reinterpret_cast<float4*>(&ws[kk][cs * 4]) = w;
        }
        #pragma unroll
        for (int i = 0; i < 2; i++) {
            int v   = tid + i * 256;
            int row = v >> 2;
            int kq  = v & 3;
            int grow = row0 + row;
            float4 xv = make_float4(0.f, 0.f, 0.f, 0.f);
            if (grow < N_NODES)
                xv = *reinterpret_cast<const float4*>(&xin[(size_t)grow * K + k0 + kq * 4]);
            xs[row][kq * 4 + 0] = make_float2(xv.x, xv.x);
            xs[row][kq * 4 + 1] = make_float2(xv.y, xv.y);
            xs[row][kq * 4 + 2] = make_float2(xv.z, xv.z);
            xs[row][kq * 4 + 3] = make_float2(xv.w, xv.w);
        }
        __syncthreads();

        #pragma unroll
        for (int kk = 0; kk < KB; kk += 2) {
            ulonglong2 w0a = *reinterpret_cast<const ulonglong2*>(&ws[kk][tx * 8]);
            ulonglong2 w0b = *reinterpret_cast<const ulonglong2*>(&ws[kk][tx * 8 + 4]);
            ulonglong2 w1a = *reinterpret_cast<const ulonglong2*>(&ws[kk + 1][tx * 8]);
            ulonglong2 w1b = *reinterpret_cast<const ulonglong2*>(&ws[kk + 1][tx * 8 + 4]);
            #pragma unroll
            for (int r = 0; r < 8; r++) {
                ulonglong2 a = *reinterpret_cast<const ulonglong2*>(&xs[ty * 8 + r][kk]);
                acc[r][0] = ffma2(a.x, w0a.x, acc[r][0]);
                acc[r][1] = ffma2(a.x, w0a.y, acc[r][1]);
                acc[r][2] = ffma2(a.x, w0b.x, acc[r][2]);
                acc[r][3] = ffma2(a.x, w0b.y, acc[r][3]);
                acc[r][0] = ffma2(a.y, w1a.x, acc[r][0]);
                acc[r][1] = ffma2(a.y, w1a.y, acc[r][1]);
                acc[r][2] = ffma2(a.y, w1b.x, acc[r][2]);
                acc[r][3] = ffma2(a.y, w1b.y, acc[r][3]);
            }
        }
    }

    float bb[8] = {0.f};
    if (tx >= 8) {
        int cb = tx * 8 - 64;
        float4 q0 = *reinterpret_cast<const float4*>(&bias[cb]);
        float4 q1 = *reinterpret_cast<const float4*>(&bias[cb + 4]);
        bb[0] = q0.x; bb[1] = q0.y; bb[2] = q0.z; bb[3] = q0.w;
        bb[4] = q1.x; bb[5] = q1.y; bb[6] = q1.z; bb[7] = q1.w;
    }
    #pragma unroll
    for (int r = 0; r < 8; r++) {
        int grow = row0 + ty * 8 + r;
        if (grow >= N_NODES) break;
        float2 c0 = *reinterpret_cast<float2*>(&acc[r][0]);
        float2 c1 = *reinterpret_cast<float2*>(&acc[r][1]);
        float2 c2 = *reinterpret_cast<float2*>(&acc[r][2]);
        float2 c3 = *reinterpret_cast<float2*>(&acc[r][3]);
        if (tx < 8) {
            // messages: convert to fp16, one 16B store of 8 halves
            __half2 hp[4];
            hp[0] = __float22half2_rn(c0);
            hp[1] = __float22half2_rn(c1);
            hp[2] = __float22half2_rn(c2);
            hp[3] = __float22half2_rn(c3);
            size_t base = (size_t)grow * HID + tx * 8;
            *reinterpret_cast<uint4*>(&yout[base]) = *reinterpret_cast<uint4*>(hp);
        } else {
            size_t base = (size_t)grow * HID + (tx * 8 - 64);
            *reinterpret_cast<float4*>(&zout[base]) =
                make_float4(c0.x + bb[0], c0.y + bb[1], c1.x + bb[2], c1.y + bb[3]);
            *reinterpret_cast<float4*>(&zout[base + 4]) =
                make_float4(c2.x + bb[4], c2.y + bb[5], c3.x + bb[6], c3.y + bb[7]);
        }
    }
}

// ---------------------------------------------------------------------------
// CSR gather: 8 threads per dst row; thread owns 8 fp16 message cols
// (one 16B load per neighbor). fp32 accumulate; h = relu(acc*inv + z).
//   FINAL=false: g_h[dst] = h                    (layer-2 input, fp32)
//   FINAL=true : out[dst] = h @ Wc + bc          (fused head)
// ---------------------------------------------------------------------------
template <bool FINAL>
__global__ void __launch_bounds__(256) k_gather(
    const __half* __restrict__ ybuf,
    const float* __restrict__ zbuf,
    const float* __restrict__ Wc,
    const float* __restrict__ bc,
    float* __restrict__ out)
{
    int t = blockIdx.x * blockDim.x + threadIdx.x;
    int dst = t >> 3;
    int part = t & 7;           // 8 cols: part*8 .. part*8+7
    if (dst >= N_NODES) return;

    int deg = g_cnt[dst];
    int n = deg < STRIDE ? deg : STRIDE;
    const int* lst = &g_csr[(size_t)dst * STRIDE];

    float2 acc[4] = {{0.f,0.f},{0.f,0.f},{0.f,0.f},{0.f,0.f}};
    int j = 0;
    for (; j + 4 <= n; j += 4) {
        int4 i0 = __ldg(reinterpret_cast<const int4*>(lst + j));
        accN(acc, i0.x, part, ybuf);
        accN(acc, i0.y, part, ybuf);
        accN(acc, i0.z, part, ybuf);
        accN(acc, i0.w, part, ybuf);
    }
    for (; j < n; j++)
        accN(acc, __ldg(&lst[j]), part, ybuf);

    float inv = 1.0f / fmaxf((float)deg, 1.0f);
    size_t zb = (size_t)dst * HID + part * 8;
    float4 z0 = *reinterpret_cast<const float4*>(&zbuf[zb]);
    float4 z1 = *reinterpret_cast<const float4*>(&zbuf[zb + 4]);

    float h0 = fmaxf(fmaf(acc[0].x, inv, z0.x), 0.f);
    float h1 = fmaxf(fmaf(acc[0].y, inv, z0.y), 0.f);
    float h2 = fmaxf(fmaf(acc[1].x, inv, z0.z), 0.f);
    float h3 = fmaxf(fmaf(acc[1].y, inv, z0.w), 0.f);
    float h4 = fmaxf(fmaf(acc[2].x, inv, z1.x), 0.f);
    float h5 = fmaxf(fmaf(acc[2].y, inv, z1.y), 0.f);
    float h6 = fmaxf(fmaf(acc[3].x, inv, z1.z), 0.f);
    float h7 = fmaxf(fmaf(acc[3].y, inv, z1.w), 0.f);

    if (!FINAL) {
        float* hb = &g_h[(size_t)dst * HID + part * 8];
        *reinterpret_cast<float4*>(hb)     = make_float4(h0, h1, h2, h3);
        *reinterpret_cast<float4*>(hb + 4) = make_float4(h4, h5, h6, h7);
    } else {
        float4 w0 = *reinterpret_cast<const float4*>(&Wc[part * 8]);
        float4 w1 = *reinterpret_cast<const float4*>(&Wc[part * 8 + 4]);
        float s = h0 * w0.x + h1 * w0.y + h2 * w0.z + h3 * w0.w
                + h4 * w1.x + h5 * w1.y + h6 * w1.z + h7 * w1.w;
        #pragma unroll
        for (int o = 4; o > 0; o >>= 1)
            s += __shfl_down_sync(0xffffffffu, s, o, 8);
        if (part == 0) out[dst] = s + __ldg(&bc[0]);
    }
}

// ---------------------------------------------------------------------------
extern "C" void kernel_launch(void* const* d_in, const int* in_sizes, int n_in,
                              void* d_out, int out_size)
{
    const float* x   = (const float*)d_in[0];
    const int*   ei  = (const int*)  d_in[1];
    const float* W1l = (const float*)d_in[2];
    const float* W1r = (const float*)d_in[3];
    const float* b1  = (const float*)d_in[4];
    const float* W2l = (const float*)d_in[5];
    const float* W2r = (const float*)d_in[6];
    const float* b2  = (const float*)d_in[7];
    const float* Wc  = (const float*)d_in[8];
    const float* bc  = (const float*)d_in[9];
    float* out = (float*)d_out;

    void *py = nullptr, *pz = nullptr, *ph = nullptr, *py2 = nullptr, *pz2 = nullptr;
    cudaGetSymbolAddress(&py,  g_y);
    cudaGetSymbolAddress(&pz,  g_z);
    cudaGetSymbolAddress(&ph,  g_h);
    cudaGetSymbolAddress(&py2, g_y2);
    cudaGetSymbolAddress(&pz2, g_z2);

    constexpr int ZC_BLKS    = (N_NODES / 4 + 255) / 256;                 // 98
    constexpr int BUILD_BLKS = (E_EDGES / 4 + 255) / 256;                 // 1563
    constexpr int GEMM_BLKS  = (N_NODES + 127) / 128;                     // 782
    constexpr int GATH_BLKS  = (int)(((size_t)N_NODES * 8 + 255) / 256);  // 3125

    // Fork: [zero_cnt -> build] overlaps gemm1 (independent pipes).
    cudaStream_t s2;
    cudaEvent_t evFork, evJoin;
    cudaStreamCreateWithFlags(&s2, cudaStreamNonBlocking);
    cudaEventCreateWithFlags(&evFork, cudaEventDisableTiming);
    cudaEventCreateWithFlags(&evJoin, cudaEventDisableTiming);

    cudaEventRecord(evFork, 0);
    cudaStreamWaitEvent(s2, evFork, 0);
    k_zero_cnt<<<ZC_BLKS, 256, 0, s2>>>();
    k_build<<<BUILD_BLKS, 256, 0, s2>>>(ei);
    cudaEventRecord(evJoin, s2);

    k_gemm<IN_DIM><<<GEMM_BLKS, 256>>>(x, W1l, W1r, b1, (__half*)py, (float*)pz);

    cudaStreamWaitEvent(0, evJoin, 0);
    k_gather<false><<<GATH_BLKS, 256>>>((const __half*)py, (const float*)pz,
                                        nullptr, nullptr, nullptr);
    k_gemm<HID><<<GEMM_BLKS, 256>>>((const float*)ph, W2l, W2r, b2,
                                    (__half*)py2, (float*)pz2);
    k_gather<true><<<GATH_BLKS, 256>>>((const __half*)py2, (const float*)pz2,
                                       Wc, bc, out);

    cudaEventDestroy(evFork);
    cudaEventDestroy(evJoin);
    cudaStreamDestroy(s2);
}

// round 10
// speedup vs baseline: 1.7429x; 1.4280x over previous
#include <cuda_runtime.h>
#include <cuda_fp16.h>
#include <cstdint>

// ---------------------------------------------------------------------------
// FloodGNN: 2-layer GraphSAGE + linear head, transform-then-aggregate.
// R10: layer-1 GEMM moved to tensor cores (mma.m16n8k16 fp16 in / fp32 acc,
// swizzled smem + ldmatrix). Layer-2 stays FFMA2 fp32. Rest = R9 skeleton.
// ---------------------------------------------------------------------------

constexpr int N_NODES = 100000;
constexpr int E_EDGES = 1600000;
constexpr int IN_DIM  = 128;
constexpr int HID     = 64;
constexpr int STRIDE  = 96;

__device__ int    g_cnt[N_NODES];
__device__ int    g_csr[(size_t)N_NODES * STRIDE];
__device__ __half g_y [(size_t)N_NODES * HID];   // layer-1 messages (fp16)
__device__ float  g_z [(size_t)N_NODES * HID];   // layer-1 self (fp32)
__device__ float  g_h [(size_t)N_NODES * HID];   // layer-2 input (fp32)
__device__ __half g_y2[(size_t)N_NODES * HID];   // layer-2 messages (fp16)
__device__ float  g_z2[(size_t)N_NODES * HID];   // layer-2 self (fp32)

// ---------------------------------------------------------------------------
__global__ void k_zero_cnt() {
    int i = blockIdx.x * blockDim.x + threadIdx.x;
    if (i < N_NODES / 4)
        reinterpret_cast<int4*>(g_cnt)[i] = make_int4(0, 0, 0, 0);
}

__global__ void k_build(const int* __restrict__ ei) {
    int i = blockIdx.x * blockDim.x + threadIdx.x;
    if (i >= E_EDGES / 4) return;
    int4 s = __ldg(reinterpret_cast<const int4*>(ei) + i);
    int4 d = __ldg(reinterpret_cast<const int4*>(ei + E_EDGES) + i);
    int slot;
    slot = atomicAdd(&g_cnt[d.x], 1); if (slot < STRIDE) g_csr[(size_t)d.x * STRIDE + slot] = s.x;
    slot = atomicAdd(&g_cnt[d.y], 1); if (slot < STRIDE) g_csr[(size_t)d.y * STRIDE + slot] = s.y;
    slot = atomicAdd(&g_cnt[d.z], 1); if (slot < STRIDE) g_csr[(size_t)d.z * STRIDE + slot] = s.z;
    slot = atomicAdd(&g_cnt[d.w], 1); if (slot < STRIDE) g_csr[(size_t)d.w * STRIDE + slot] = s.w;
}

// ---------------------------------------------------------------------------
__device__ __forceinline__ unsigned long long ffma2(
    unsigned long long a, unsigned long long b, unsigned long long c)
{
    unsigned long long d;
    asm("fma.rn.f32x2 %0, %1, %2, %3;" : "=l"(d) : "l"(a), "l"(b), "l"(c));
    return d;
}

__device__ __forceinline__ uint32_t smem_u32(const void* p) {
    return (uint32_t)__cvta_generic_to_shared(p);
}
__device__ __forceinline__ void ldsm_x4(uint32_t& r0, uint32_t& r1,
                                        uint32_t& r2, uint32_t& r3, uint32_t a) {
    asm volatile("ldmatrix.sync.aligned.m8n8.x4.shared.b16 {%0,%1,%2,%3}, [%4];"
                 : "=r"(r0), "=r"(r1), "=r"(r2), "=r"(r3) : "r"(a));
}
__device__ __forceinline__ void ldsm_x4_t(uint32_t& r0, uint32_t& r1,
                                          uint32_t& r2, uint32_t& r3, uint32_t a) {
    asm volatile("ldmatrix.sync.aligned.m8n8.x4.trans.shared.b16 {%0,%1,%2,%3}, [%4];"
                 : "=r"(r0), "=r"(r1), "=r"(r2), "=r"(r3) : "r"(a));
}
__device__ __forceinline__ void mma16816(float d[4], const uint32_t a[4],
                                         uint32_t b0, uint32_t b1) {
    asm volatile(
        "mma.sync.aligned.m16n8k16.row.col.f32.f16.f16.f32 "
        "{%0,%1,%2,%3}, {%4,%5,%6,%7}, {%8,%9}, {%0,%1,%2,%3};"
        : "+f"(d[0]), "+f"(d[1]), "+f"(d[2]), "+f"(d[3])
        : "r"(a[0]), "r"(a[1]), "r"(a[2]), "r"(a[3]), "r"(b0), "r"(b1));
}

// Accumulate one neighbor's 8 fp16 message cols into 4 fp32 float2 accs.
__device__ __forceinline__ void accN(float2 acc[4], int src, int part,
                                     const __half* __restrict__ ybuf)
{
    uint4 a = __ldg(reinterpret_cast<const uint4*>(&ybuf[(size_t)src * HID + part * 8]));
    const __half2* ah = reinterpret_cast<const __half2*>(&a);
    #pragma unroll
    for (int q = 0; q < 4; q++) {
        float2 f = __half22float2(ah[q]);
        acc[q].x += f.x;
        acc[q].y += f.y;
    }
}

// ---------------------------------------------------------------------------
// Layer-1 tensor-core GEMM. Per 128-row block:
//   g_y[row] = half( x[row] @ W1l )        (cols 0-63 of the 128-wide tile)
//   g_z[row] = x[row] @ W1r + b1  (fp32)   (cols 64-127)
// x and W converted to fp16 in smem; 8-half-unit XOR swizzle; ldmatrix + mma.
// Warp w owns rows [w*16, w*16+16) x all 128 cols (16 n-chunks of 8).
// ---------------------------------------------------------------------------
constexpr int SMEM_TC = 2 * 128 * 128 * (int)sizeof(__half);   // 64 KB

__global__ void __launch_bounds__(256, 2) k_gemm1_tc(
    const float* __restrict__ xin,
    const float* __restrict__ Wl,
    const float* __restrict__ Wr,
    const float* __restrict__ bias,
    __half* __restrict__ yout,
    float* __restrict__ zout)
{
    extern __shared__ __half sm[];
    __half* sx = sm;               // [128 rows][128 k]  (swizzled units)
    __half* sw = sm + 128 * 128;   // [128 k][128 cols]  (swizzled units)

    const int tid = threadIdx.x;
    const int row0 = blockIdx.x * 128;

    // ---- stage x: f32 -> f16, unit-swizzled ----
    #pragma unroll
    for (int i = 0; i < 8; i++) {
        int t = tid + i * 256;           // [0,2048): (row, unit)
        int r = t >> 4, u = t & 15;
        int grow = row0 + r;
        float4 f0 = make_float4(0.f, 0.f, 0.f, 0.f);
        float4 f1 = make_float4(0.f, 0.f, 0.f, 0.f);
        if (grow < N_NODES) {
            const float* p = &xin[(size_t)grow * IN_DIM + u * 8];
            f0 = *reinterpret_cast<const float4*>(p);
            f1 = *reinterpret_cast<const float4*>(p + 4);
        }
        __half2 h[4];
        h[0] = __floats2half2_rn(f0.x, f0.y);
        h[1] = __floats2half2_rn(f0.z, f0.w);
        h[2] = __floats2half2_rn(f1.x, f1.y);
        h[3] = __floats2half2_rn(f1.z, f1.w);
        int su = u ^ (r & 7);
        *reinterpret_cast<uint4*>(&sx[r * 128 + su * 8]) = *reinterpret_cast<uint4*>(h);
    }
    // ---- stage W (Wl cols 0-63 | Wr cols 64-127): f32 -> f16, swizzled ----
    #pragma unroll
    for (int i = 0; i < 8; i++) {
        int t = tid + i * 256;           // [0,2048): (k, unit)
        int k = t >> 4, u = t & 15;
        const float* p = (u < 8) ? &Wl[k * HID + u * 8] : &Wr[k * HID + (u - 8) * 8];
        float4 f0 = *reinterpret_cast<const float4*>(p);
        float4 f1 = *reinterpret_cast<const float4*>(p + 4);
        __half2 h[4];
        h[0] = __floats2half2_rn(f0.x, f0.y);
        h[1] = __floats2half2_rn(f0.z, f0.w);
        h[2] = __floats2half2_rn(f1.x, f1.y);
        h[3] = __floats2half2_rn(f1.z, f1.w);
        int su = u ^ (k & 7);
        *reinterpret_cast<uint4*>(&sw[k * 128 + su * 8]) = *reinterpret_cast<uint4*>(h);
    }
    __syncthreads();

    const int warp = tid >> 5;
    const int lane = tid & 31;
    const int mrow = warp * 16;

    float d[16][4];
    #pragma unroll
    for (int j = 0; j < 16; j++)
        #pragma unroll
        for (int q = 0; q < 4; q++) d[j][q] = 0.f;

    const uint32_t sx_base = smem_u32(sx);
    const uint32_t sw_base = smem_u32(sw);

    #pragma unroll
    for (int k0 = 0; k0 < IN_DIM; k0 += 16) {
        // A fragment: rows mrow..mrow+15, k-cols k0..k0+15
        uint32_t a[4];
        {
            int r  = mrow + (lane & 15);
            int cu = (k0 >> 3) + (lane >> 4);
            uint32_t addr = sx_base + (uint32_t)(r * 128 + ((cu ^ (r & 7)) * 8)) * 2u;
            ldsm_x4(a[0], a[1], a[2], a[3], addr);
        }
        #pragma unroll
        for (int nc = 0; nc < 8; nc++) {       // 16 cols per iteration
            int k  = k0 + (lane & 15);
            int bu = nc * 2 + (lane >> 4);
            uint32_t addr = sw_base + (uint32_t)(k * 128 + ((bu ^ (k & 7)) * 8)) * 2u;
            uint32_t b0, b1, b2, b3;
            ldsm_x4_t(b0, b1, b2, b3, addr);
            mma16816(d[nc * 2],     a, b0, b1);
            mma16816(d[nc * 2 + 1], a, b2, b3);
        }
    }

    // ---- epilogue: lane owns cols (tig*2, tig*2+1), rows g and g+8 ----
    const int g   = lane >> 2;
    const int tig = lane & 3;
    const int ra  = row0 + mrow + g;
    const int rb  = ra + 8;
    #pragma unroll
    for (int jj = 0; jj < 16; jj++) {
        int c = jj * 8 + tig * 2;
        if (c < HID) {
            __half2 va = __floats2half2_rn(d[jj][0], d[jj][1]);
            __half2 vb = __floats2half2_rn(d[jj][2], d[jj][3]);
            if (ra < N_NODES) *reinterpret_cast<__half2*>(&yout[(size_t)ra * HID + c]) = va;
            if (rb < N_NODES) *reinterpret_cast<__half2*>(&yout[(size_t)rb * HID + c]) = vb;
        } else {
            int cz = c - HID;
            float bx = __ldg(&bias[cz]);
            float by = __ldg(&bias[cz + 1]);
            if (ra < N_NODES)
                *reinterpret_cast<float2*>(&zout[(size_t)ra * HID + cz]) =
                    make_float2(d[jj][0] + bx, d[jj][1] + by);
            if (rb < N_NODES)
                *reinterpret_cast<float2*>(&zout[(size_t)rb * HID + cz]) =
                    make_float2(d[jj][2] + bx, d[jj][3] + by);
        }
    }
}

// ---------------------------------------------------------------------------
// Layer-2 FFMA2 GEMM (fp32 in, y fp16 out / z fp32 out). K = HID = 64.
// ---------------------------------------------------------------------------
template <int K>
__global__ void __launch_bounds__(256, 2) k_gemm(
    const float* __restrict__ xin,
    const float* __restrict__ Wl,
    const float* __restrict__ Wr,
    const float* __restrict__ bias,
    __half* __restrict__ yout,
    float* __restrict__ zout)
{
    constexpr int KB = 16;
    constexpr int NSLAB = K / KB;
    __shared__ float2 xs[128][KB + 2];
    __shared__ float  ws[KB][128];

    const int tid = threadIdx.x;
    const int tx = tid & 15;
    const int ty = tid >> 4;
    const int row0 = blockIdx.x * 128;

    unsigned long long acc[8][4];
    #pragma unroll
    for (int r = 0; r < 8; r++)
        #pragma unroll
        for (int c = 0; c < 4; c++) acc[r][c] = 0ULL;

    for (int slab = 0; slab < NSLAB; slab++) {
        const int k0 = slab * KB;
        __syncthreads();
        #pragma unroll
        for (int i = 0; i < 2; i++) {
            int v  = tid + i * 256;
            int kk = v >> 5;
            int cs = v & 31;
            int gk = k0 + kk;
            float4 w;
            if (cs < 16) w = *reinterpret_cast<const float4*>(&Wl[gk * HID + cs * 4]);
            else         w = *reinterpret_cast<const float4*>(&Wr[gk * HID + (cs - 16) * 4]);
            *reinterpret_cast<float4*>(&ws[kk][cs * 4]) = w;
        }
        #pragma unroll
        for (int i = 0; i < 2; i++) {
            int v   = tid + i * 256;
            int row = v >> 2;
            int kq  = v & 3;
            int grow = row0 + row;
            float4 xv = make_float4(0.f, 0.f, 0.f, 0.f);
            if (grow < N_NODES)
                xv = *reinterpret_cast<const float4*>(&xin[(size_t)grow * K + k0 + kq * 4]);
            xs[row][kq * 4 + 0] = make_float2(xv.x, xv.x);
            xs[row][kq * 4 + 1] = make_float2(xv.y, xv.y);
            xs[row][kq * 4 + 2] = make_float2(xv.z, xv.z);
            xs[row][kq * 4 + 3] = make_float2(xv.w, xv.w);
        }
        __syncthreads();

        #pragma unroll
        for (int kk = 0; kk < KB; kk += 2) {
            ulonglong2 w0a = *reinterpret_cast<const ulonglong2*>(&ws[kk][tx * 8]);
            ulonglong2 w0b = *reinterpret_cast<const ulonglong2*>(&ws[kk][tx * 8 + 4]);
            ulonglong2 w1a = *reinterpret_cast<const ulonglong2*>(&ws[kk + 1][tx * 8]);
            ulonglong2 w1b = *reinterpret_cast<const ulonglong2*>(&ws[kk + 1][tx * 8 + 4]);
            #pragma unroll
            for (int r = 0; r < 8; r++) {
                ulonglong2 a = *reinterpret_cast<const ulonglong2*>(&xs[ty * 8 + r][kk]);
                acc[r][0] = ffma2(a.x, w0a.x, acc[r][0]);
                acc[r][1] = ffma2(a.x, w0a.y, acc[r][1]);
                acc[r][2] = ffma2(a.x, w0b.x, acc[r][2]);
                acc[r][3] = ffma2(a.x, w0b.y, acc[r][3]);
                acc[r][0] = ffma2(a.y, w1a.x, acc[r][0]);
                acc[r][1] = ffma2(a.y, w1a.y, acc[r][1]);
                acc[r][2] = ffma2(a.y, w1b.x, acc[r][2]);
                acc[r][3] = ffma2(a.y, w1b.y, acc[r][3]);
            }
        }
    }

    float bb[8] = {0.f};
    if (tx >= 8) {
        int cb = tx * 8 - 64;
        float4 q0 = *reinterpret_cast<const float4*>(&bias[cb]);
        float4 q1 = *reinterpret_cast<const float4*>(&bias[cb + 4]);
        bb[0] = q0.x; bb[1] = q0.y; bb[2] = q0.z; bb[3] = q0.w;
        bb[4] = q1.x; bb[5] = q1.y; bb[6] = q1.z; bb[7] = q1.w;
    }
    #pragma unroll
    for (int r = 0; r < 8; r++) {
        int grow = row0 + ty * 8 + r;
        if (grow >= N_NODES) break;
        float2 c0 = *reinterpret_cast<float2*>(&acc[r][0]);
        float2 c1 = *reinterpret_cast<float2*>(&acc[r][1]);
        float2 c2 = *reinterpret_cast<float2*>(&acc[r][2]);
        float2 c3 = *reinterpret_cast<float2*>(&acc[r][3]);
        if (tx < 8) {
            __half2 hp[4];
            hp[0] = __float22half2_rn(c0);
            hp[1] = __float22half2_rn(c1);
            hp[2] = __float22half2_rn(c2);
            hp[3] = __float22half2_rn(c3);
            size_t base = (size_t)grow * HID + tx * 8;
            *reinterpret_cast<uint4*>(&yout[base]) = *reinterpret_cast<uint4*>(hp);
        } else {
            size_t base = (size_t)grow * HID + (tx * 8 - 64);
            *reinterpret_cast<float4*>(&zout[base]) =
                make_float4(c0.x + bb[0], c0.y + bb[1], c1.x + bb[2], c1.y + bb[3]);
            *reinterpret_cast<float4*>(&zout[base + 4]) =
                make_float4(c2.x + bb[4], c2.y + bb[5], c3.x + bb[6], c3.y + bb[7]);
        }
    }
}

// ---------------------------------------------------------------------------
// CSR gather: 8 threads per dst row; thread owns 8 fp16 message cols.
// ---------------------------------------------------------------------------
template <bool FINAL>
__global__ void __launch_bounds__(256) k_gather(
    const __half* __restrict__ ybuf,
    const float* __restrict__ zbuf,
    const float* __restrict__ Wc,
    const float* __restrict__ bc,
    float* __restrict__ out)
{
    int t = blockIdx.x * blockDim.x + threadIdx.x;
    int dst = t >> 3;
    int part = t & 7;
    if (dst >= N_NODES) return;

    int deg = g_cnt[dst];
    int n = deg < STRIDE ? deg : STRIDE;
    const int* lst = &g_csr[(size_t)dst * STRIDE];

    float2 acc[4] = {{0.f,0.f},{0.f,0.f},{0.f,0.f},{0.f,0.f}};
    int j = 0;
    for (; j + 4 <= n; j += 4) {
        int4 i0 = __ldg(reinterpret_cast<const int4*>(lst + j));
        accN(acc, i0.x, part, ybuf);
        accN(acc, i0.y, part, ybuf);
        accN(acc, i0.z, part, ybuf);
        accN(acc, i0.w, part, ybuf);
    }
    for (; j < n; j++)
        accN(acc, __ldg(&lst[j]), part, ybuf);

    float inv = 1.0f / fmaxf((float)deg, 1.0f);
    size_t zb = (size_t)dst * HID + part * 8;
    float4 z0 = *reinterpret_cast<const float4*>(&zbuf[zb]);
    float4 z1 = *reinterpret_cast<const float4*>(&zbuf[zb + 4]);

    float h0 = fmaxf(fmaf(acc[0].x, inv, z0.x), 0.f);
    float h1 = fmaxf(fmaf(acc[0].y, inv, z0.y), 0.f);
    float h2 = fmaxf(fmaf(acc[1].x, inv, z0.z), 0.f);
    float h3 = fmaxf(fmaf(acc[1].y, inv, z0.w), 0.f);
    float h4 = fmaxf(fmaf(acc[2].x, inv, z1.x), 0.f);
    float h5 = fmaxf(fmaf(acc[2].y, inv, z1.y), 0.f);
    float h6 = fmaxf(fmaf(acc[3].x, inv, z1.z), 0.f);
    float h7 = fmaxf(fmaf(acc[3].y, inv, z1.w), 0.f);

    if (!FINAL) {
        float* hb = &g_h[(size_t)dst * HID + part * 8];
        *reinterpret_cast<float4*>(hb)     = make_float4(h0, h1, h2, h3);
        *reinterpret_cast<float4*>(hb + 4) = make_float4(h4, h5, h6, h7);
    } else {
        float4 w0 = *reinterpret_cast<const float4*>(&Wc[part * 8]);
        float4 w1 = *reinterpret_cast<const float4*>(&Wc[part * 8 + 4]);
        float s = h0 * w0.x + h1 * w0.y + h2 * w0.z + h3 * w0.w
                + h4 * w1.x + h5 * w1.y + h6 * w1.z + h7 * w1.w;
        #pragma unroll
        for (int o = 4; o > 0; o >>= 1)
            s += __shfl_down_sync(0xffffffffu, s, o, 8);
        if (part == 0) out[dst] = s + __ldg(&bc[0]);
    }
}

// ---------------------------------------------------------------------------
extern "C" void kernel_launch(void* const* d_in, const int* in_sizes, int n_in,
                              void* d_out, int out_size)
{
    const float* x   = (const float*)d_in[0];
    const int*   ei  = (const int*)  d_in[1];
    const float* W1l = (const float*)d_in[2];
    const float* W1r = (const float*)d_in[3];
    const float* b1  = (const float*)d_in[4];
    const float* W2l = (const float*)d_in[5];
    const float* W2r = (const float*)d_in[6];
    const float* b2  = (const float*)d_in[7];
    const float* Wc  = (const float*)d_in[8];
    const float* bc  = (const float*)d_in[9];
    float* out = (float*)d_out;

    void *py = nullptr, *pz = nullptr, *ph = nullptr, *py2 = nullptr, *pz2 = nullptr;
    cudaGetSymbolAddress(&py,  g_y);
    cudaGetSymbolAddress(&pz,  g_z);
    cudaGetSymbolAddress(&ph,  g_h);
    cudaGetSymbolAddress(&py2, g_y2);
    cudaGetSymbolAddress(&pz2, g_z2);

    cudaFuncSetAttribute(k_gemm1_tc,
                         cudaFuncAttributeMaxDynamicSharedMemorySize, SMEM_TC);

    constexpr int ZC_BLKS    = (N_NODES / 4 + 255) / 256;                 // 98
    constexpr int BUILD_BLKS = (E_EDGES / 4 + 255) / 256;                 // 1563
    constexpr int GEMM_BLKS  = (N_NODES + 127) / 128;                     // 782
    constexpr int GATH_BLKS  = (int)(((size_t)N_NODES * 8 + 255) / 256);  // 3125

    // Fork: [zero_cnt -> build] overlaps gemm1 (independent pipes).
    cudaStream_t s2;
    cudaEvent_t evFork, evJoin;
    cudaStreamCreateWithFlags(&s2, cudaStreamNonBlocking);
    cudaEventCreateWithFlags(&evFork, cudaEventDisableTiming);
    cudaEventCreateWithFlags(&evJoin, cudaEventDisableTiming);

    cudaEventRecord(evFork, 0);
    cudaStreamWaitEvent(s2, evFork, 0);
    k_zero_cnt<<<ZC_BLKS, 256, 0, s2>>>();
    k_build<<<BUILD_BLKS, 256, 0, s2>>>(ei);
    cudaEventRecord(evJoin, s2);

    k_gemm1_tc<<<GEMM_BLKS, 256, SMEM_TC>>>(x, W1l, W1r, b1,
                                            (__half*)py, (float*)pz);

    cudaStreamWaitEvent(0, evJoin, 0);
    k_gather<false><<<GATH_BLKS, 256>>>((const __half*)py, (const float*)pz,
                                        nullptr, nullptr, nullptr);
    k_gemm<HID><<<GEMM_BLKS, 256>>>((const float*)ph, W2l, W2r, b2,
                                    (__half*)py2, (float*)pz2);
    k_gather<true><<<GATH_BLKS, 256>>>((const __half*)py2, (const float*)pz2,
                                       Wc, bc, out);

    cudaEventDestroy(evFork);
    cudaEventDestroy(evJoin);
    cudaStreamDestroy(s2);
}

// round 11
// speedup vs baseline: 2.2275x; 1.2780x over previous
#include <cuda_runtime.h>
#include <cuda_fp16.h>
#include <cstdint>

// ---------------------------------------------------------------------------
// FloodGNN: 2-layer GraphSAGE + linear head, transform-then-aggregate.
// R11: BOTH dense transforms on tensor cores (mma.m16n8k16, fp16 in/fp32 acc).
// gather<0> emits h1 as fp16 so layer-2 staging is a pure swizzled copy.
// Skeleton: stream-fork build, 8-thread/row fp16 gathers, fused head.
// ---------------------------------------------------------------------------

constexpr int N_NODES = 100000;
constexpr int E_EDGES = 1600000;
constexpr int IN_DIM  = 128;
constexpr int HID     = 64;
constexpr int STRIDE  = 96;

__device__ int    g_cnt[N_NODES];
__device__ int    g_csr[(size_t)N_NODES * STRIDE];
__device__ __half g_y [(size_t)N_NODES * HID];   // layer-1 messages (fp16)
__device__ float  g_z [(size_t)N_NODES * HID];   // layer-1 self (fp32)
__device__ __half g_h [(size_t)N_NODES * HID];   // layer-2 input (fp16)
__device__ __half g_y2[(size_t)N_NODES * HID];   // layer-2 messages (fp16)
__device__ float  g_z2[(size_t)N_NODES * HID];   // layer-2 self (fp32)

// ---------------------------------------------------------------------------
__global__ void k_zero_cnt() {
    int i = blockIdx.x * blockDim.x + threadIdx.x;
    if (i < N_NODES / 4)
        reinterpret_cast<int4*>(g_cnt)[i] = make_int4(0, 0, 0, 0);
}

__global__ void k_build(const int* __restrict__ ei) {
    int i = blockIdx.x * blockDim.x + threadIdx.x;
    if (i >= E_EDGES / 4) return;
    int4 s = __ldg(reinterpret_cast<const int4*>(ei) + i);
    int4 d = __ldg(reinterpret_cast<const int4*>(ei + E_EDGES) + i);
    int slot;
    slot = atomicAdd(&g_cnt[d.x], 1); if (slot < STRIDE) g_csr[(size_t)d.x * STRIDE + slot] = s.x;
    slot = atomicAdd(&g_cnt[d.y], 1); if (slot < STRIDE) g_csr[(size_t)d.y * STRIDE + slot] = s.y;
    slot = atomicAdd(&g_cnt[d.z], 1); if (slot < STRIDE) g_csr[(size_t)d.z * STRIDE + slot] = s.z;
    slot = atomicAdd(&g_cnt[d.w], 1); if (slot < STRIDE) g_csr[(size_t)d.w * STRIDE + slot] = s.w;
}

// ---------------------------------------------------------------------------
__device__ __forceinline__ uint32_t smem_u32(const void* p) {
    return (uint32_t)__cvta_generic_to_shared(p);
}
__device__ __forceinline__ void ldsm_x4(uint32_t& r0, uint32_t& r1,
                                        uint32_t& r2, uint32_t& r3, uint32_t a) {
    asm volatile("ldmatrix.sync.aligned.m8n8.x4.shared.b16 {%0,%1,%2,%3}, [%4];"
                 : "=r"(r0), "=r"(r1), "=r"(r2), "=r"(r3) : "r"(a));
}
__device__ __forceinline__ void ldsm_x4_t(uint32_t& r0, uint32_t& r1,
                                          uint32_t& r2, uint32_t& r3, uint32_t a) {
    asm volatile("ldmatrix.sync.aligned.m8n8.x4.trans.shared.b16 {%0,%1,%2,%3}, [%4];"
                 : "=r"(r0), "=r"(r1), "=r"(r2), "=r"(r3) : "r"(a));
}
__device__ __forceinline__ void mma16816(float d[4], const uint32_t a[4],
                                         uint32_t b0, uint32_t b1) {
    asm volatile(
        "mma.sync.aligned.m16n8k16.row.col.f32.f16.f16.f32 "
        "{%0,%1,%2,%3}, {%4,%5,%6,%7}, {%8,%9}, {%0,%1,%2,%3};"
        : "+f"(d[0]), "+f"(d[1]), "+f"(d[2]), "+f"(d[3])
        : "r"(a[0]), "r"(a[1]), "r"(a[2]), "r"(a[3]), "r"(b0), "r"(b1));
}

// Accumulate one neighbor's 8 fp16 message cols into 4 fp32 float2 accs.
__device__ __forceinline__ void accN(float2 acc[4], int src, int part,
                                     const __half* __restrict__ ybuf)
{
    uint4 a = __ldg(reinterpret_cast<const uint4*>(&ybuf[(size_t)src * HID + part * 8]));
    const __half2* ah = reinterpret_cast<const __half2*>(&a);
    #pragma unroll
    for (int q = 0; q < 4; q++) {
        float2 f = __half22float2(ah[q]);
        acc[q].x += f.x;
        acc[q].y += f.y;
    }
}

// ---------------------------------------------------------------------------
// Tensor-core transform. Per 128-row block:
//   yout[row] = half( feat[row] @ Wl )       (tile cols 0-63)
//   zout[row] = feat[row] @ Wr + bias (fp32) (tile cols 64-127)
// Tin = float (layer 1, K=128, converts during staging) or __half (layer 2,
// K=64, pure swizzled copy). 8-half-unit XOR swizzle; ldmatrix + mma.
// Warp w owns rows [w*16, w*16+16) x all 128 tile cols.
// ---------------------------------------------------------------------------
template <int K, typename Tin>
__global__ void __launch_bounds__(256, 2) k_gemm_tc(
    const Tin* __restrict__ xin,
    const float* __restrict__ Wl,
    const float* __restrict__ Wr,
    const float* __restrict__ bias,
    __half* __restrict__ yout,
    float* __restrict__ zout)
{
    extern __shared__ __half sm[];
    __half* sx = sm;               // [128 rows][K]   (swizzled 8-half units)
    __half* sw = sm + 128 * K;     // [K][128 cols]   (swizzled 8-half units)

    const int tid = threadIdx.x;
    const int row0 = blockIdx.x * 128;
    constexpr int XU = K / 8;      // x units per row (16 or 8)

    // ---- stage x ----
    #pragma unroll
    for (int i = 0; i < (128 * XU) / 256; i++) {
        int t = tid + i * 256;
        int r = t / XU, u = t % XU;
        int grow = row0 + r;
        uint4 pkt;
        if constexpr (sizeof(Tin) == 4) {
            float4 f0 = make_float4(0.f, 0.f, 0.f, 0.f);
            float4 f1 = make_float4(0.f, 0.f, 0.f, 0.f);
            if (grow < N_NODES) {
                const float* p = reinterpret_cast<const float*>(xin) + (size_t)grow * K + u * 8;
                f0 = *reinterpret_cast<const float4*>(p);
                f1 = *reinterpret_cast<const float4*>(p + 4);
            }
            __half2 h[4];
            h[0] = __floats2half2_rn(f0.x, f0.y);
            h[1] = __floats2half2_rn(f0.z, f0.w);
            h[2] = __floats2half2_rn(f1.x, f1.y);
            h[3] = __floats2half2_rn(f1.z, f1.w);
            pkt = *reinterpret_cast<uint4*>(h);
        } else {
            pkt = make_uint4(0u, 0u, 0u, 0u);
            if (grow < N_NODES)
                pkt = __ldg(reinterpret_cast<const uint4*>(
                    reinterpret_cast<const __half*>(xin) + (size_t)grow * K + u * 8));
        }
        int su = u ^ (r & 7);
        *reinterpret_cast<uint4*>(&sx[r * K + su * 8]) = pkt;
    }
    // ---- stage W (Wl -> tile cols 0-63, Wr -> 64-127), f32 -> f16 ----
    #pragma unroll
    for (int i = 0; i < (K * 16) / 256; i++) {
        int t = tid + i * 256;
        int k = t >> 4, u = t & 15;
        const float* p = (u < 8) ? &Wl[k * HID + u * 8] : &Wr[k * HID + (u - 8) * 8];
        float4 f0 = *reinterpret_cast<const float4*>(p);
        float4 f1 = *reinterpret_cast<const float4*>(p + 4);
        __half2 h[4];
        h[0] = __floats2half2_rn(f0.x, f0.y);
        h[1] = __floats2half2_rn(f0.z, f0.w);
        h[2] = __floats2half2_rn(f1.x, f1.y);
        h[3] = __floats2half2_rn(f1.z, f1.w);
        int su = u ^ (k & 7);
        *reinterpret_cast<uint4*>(&sw[k * 128 + su * 8]) = *reinterpret_cast<uint4*>(h);
    }
    __syncthreads();

    const int warp = tid >> 5;
    const int lane = tid & 31;
    const int mrow = warp * 16;

    float d[16][4];
    #pragma unroll
    for (int j = 0; j < 16; j++)
        #pragma unroll
        for (int q = 0; q < 4; q++) d[j][q] = 0.f;

    const uint32_t sx_base = smem_u32(sx);
    const uint32_t sw_base = smem_u32(sw);

    #pragma unroll
    for (int k0 = 0; k0 < K; k0 += 16) {
        uint32_t a[4];
        {
            int r  = mrow + (lane & 15);
            int cu = (k0 >> 3) + (lane >> 4);
            uint32_t addr = sx_base + (uint32_t)(r * K + ((cu ^ (r & 7)) * 8)) * 2u;
            ldsm_x4(a[0], a[1], a[2], a[3], addr);
        }
        #pragma unroll
        for (int nc = 0; nc < 8; nc++) {
            int k  = k0 + (lane & 15);
            int bu = nc * 2 + (lane >> 4);
            uint32_t addr = sw_base + (uint32_t)(k * 128 + ((bu ^ (k & 7)) * 8)) * 2u;
            uint32_t b0, b1, b2, b3;
            ldsm_x4_t(b0, b1, b2, b3, addr);
            mma16816(d[nc * 2],     a, b0, b1);
            mma16816(d[nc * 2 + 1], a, b2, b3);
        }
    }

    // ---- epilogue: lane owns cols (tig*2, tig*2+1), rows g and g+8 ----
    const int g   = lane >> 2;
    const int tig = lane & 3;
    const int ra  = row0 + mrow + g;
    const int rb  = ra + 8;
    #pragma unroll
    for (int jj = 0; jj < 16; jj++) {
        int c = jj * 8 + tig * 2;
        if (c < HID) {
            __half2 va = __floats2half2_rn(d[jj][0], d[jj][1]);
            __half2 vb = __floats2half2_rn(d[jj][2], d[jj][3]);
            if (ra < N_NODES) *reinterpret_cast<__half2*>(&yout[(size_t)ra * HID + c]) = va;
            if (rb < N_NODES) *reinterpret_cast<__half2*>(&yout[(size_t)rb * HID + c]) = vb;
        } else {
            int cz = c - HID;
            float bx = __ldg(&bias[cz]);
            float by = __ldg(&bias[cz + 1]);
            if (ra < N_NODES)
                *reinterpret_cast<float2*>(&zout[(size_t)ra * HID + cz]) =
                    make_float2(d[jj][0] + bx, d[jj][1] + by);
            if (rb < N_NODES)
                *reinterpret_cast<float2*>(&zout[(size_t)rb * HID + cz]) =
                    make_float2(d[jj][2] + bx, d[jj][3] + by);
        }
    }
}

constexpr int SMEM_TC1 = 2 * 128 * IN_DIM * (int)sizeof(__half);  // 64 KB
constexpr int SMEM_TC2 = 2 * 128 * HID * (int)sizeof(__half);     // 32 KB

// ---------------------------------------------------------------------------
// CSR gather: 8 threads per dst row; thread owns 8 fp16 message cols.
// acc = sum(y[neigh]) fp32; h = relu(acc*inv + z).
//   FINAL=false: g_h[dst] = half(h)              (layer-2 input, fp16)
//   FINAL=true : out[dst] = h @ Wc + bc          (fused head)
// ---------------------------------------------------------------------------
template <bool FINAL>
__global__ void __launch_bounds__(256) k_gather(
    const __half* __restrict__ ybuf,
    const float* __restrict__ zbuf,
    const float* __restrict__ Wc,
    const float* __restrict__ bc,
    float* __restrict__ out)
{
    int t = blockIdx.x * blockDim.x + threadIdx.x;
    int dst = t >> 3;
    int part = t & 7;
    if (dst >= N_NODES) return;

    int deg = g_cnt[dst];
    int n = deg < STRIDE ? deg : STRIDE;
    const int* lst = &g_csr[(size_t)dst * STRIDE];

    float2 acc[4] = {{0.f,0.f},{0.f,0.f},{0.f,0.f},{0.f,0.f}};
    int j = 0;
    for (; j + 4 <= n; j += 4) {
        int4 i0 = __ldg(reinterpret_cast<const int4*>(lst + j));
        accN(acc, i0.x, part, ybuf);
        accN(acc, i0.y, part, ybuf);
        accN(acc, i0.z, part, ybuf);
        accN(acc, i0.w, part, ybuf);
    }
    for (; j < n; j++)
        accN(acc, __ldg(&lst[j]), part, ybuf);

    float inv = 1.0f / fmaxf((float)deg, 1.0f);
    size_t zb = (size_t)dst * HID + part * 8;
    float4 z0 = *reinterpret_cast<const float4*>(&zbuf[zb]);
    float4 z1 = *reinterpret_cast<const float4*>(&zbuf[zb + 4]);

    float h0 = fmaxf(fmaf(acc[0].x, inv, z0.x), 0.f);
    float h1 = fmaxf(fmaf(acc[0].y, inv, z0.y), 0.f);
    float h2 = fmaxf(fmaf(acc[1].x, inv, z0.z), 0.f);
    float h3 = fmaxf(fmaf(acc[1].y, inv, z0.w), 0.f);
    float h4 = fmaxf(fmaf(acc[2].x, inv, z1.x), 0.f);
    float h5 = fmaxf(fmaf(acc[2].y, inv, z1.y), 0.f);
    float h6 = fmaxf(fmaf(acc[3].x, inv, z1.z), 0.f);
    float h7 = fmaxf(fmaf(acc[3].y, inv, z1.w), 0.f);

    if (!FINAL) {
        __half2 hp[4];
        hp[0] = __floats2half2_rn(h0, h1);
        hp[1] = __floats2half2_rn(h2, h3);
        hp[2] = __floats2half2_rn(h4, h5);
        hp[3] = __floats2half2_rn(h6, h7);
        *reinterpret_cast<uint4*>(&g_h[(size_t)dst * HID + part * 8]) =
            *reinterpret_cast<uint4*>(hp);
    } else {
        float4 w0 = *reinterpret_cast<const float4*>(&Wc[part * 8]);
        float4 w1 = *reinterpret_cast<const float4*>(&Wc[part * 8 + 4]);
        float s = h0 * w0.x + h1 * w0.y + h2 * w0.z + h3 * w0.w
                + h4 * w1.x + h5 * w1.y + h6 * w1.z + h7 * w1.w;
        #pragma unroll
        for (int o = 4; o > 0; o >>= 1)
            s += __shfl_down_sync(0xffffffffu, s, o, 8);
        if (part == 0) out[dst] = s + __ldg(&bc[0]);
    }
}

// ---------------------------------------------------------------------------
extern "C" void kernel_launch(void* const* d_in, const int* in_sizes, int n_in,
                              void* d_out, int out_size)
{
    const float* x   = (const float*)d_in[0];
    const int*   ei  = (const int*)  d_in[1];
    const float* W1l = (const float*)d_in[2];
    const float* W1r = (const float*)d_in[3];
    const float* b1  = (const float*)d_in[4];
    const float* W2l = (const float*)d_in[5];
    const float* W2r = (const float*)d_in[6];
    const float* b2  = (const float*)d_in[7];
    const float* Wc  = (const float*)d_in[8];
    const float* bc  = (const float*)d_in[9];
    float* out = (float*)d_out;

    void *py = nullptr, *pz = nullptr, *ph = nullptr, *py2 = nullptr, *pz2 = nullptr;
    cudaGetSymbolAddress(&py,  g_y);
    cudaGetSymbolAddress(&pz,  g_z);
    cudaGetSymbolAddress(&ph,  g_h);
    cudaGetSymbolAddress(&py2, g_y2);
    cudaGetSymbolAddress(&pz2, g_z2);

    cudaFuncSetAttribute((const void*)&k_gemm_tc<IN_DIM, float>,
                         cudaFuncAttributeMaxDynamicSharedMemorySize, SMEM_TC1);
    cudaFuncSetAttribute((const void*)&k_gemm_tc<HID, __half>,
                         cudaFuncAttributeMaxDynamicSharedMemorySize, SMEM_TC2);

    constexpr int ZC_BLKS    = (N_NODES / 4 + 255) / 256;                 // 98
    constexpr int BUILD_BLKS = (E_EDGES / 4 + 255) / 256;                 // 1563
    constexpr int GEMM_BLKS  = (N_NODES + 127) / 128;                     // 782
    constexpr int GATH_BLKS  = (int)(((size_t)N_NODES * 8 + 255) / 256);  // 3125

    // Fork: [zero_cnt -> build] overlaps gemm1 (independent pipes).
    cudaStream_t s2;
    cudaEvent_t evFork, evJoin;
    cudaStreamCreateWithFlags(&s2, cudaStreamNonBlocking);
    cudaEventCreateWithFlags(&evFork, cudaEventDisableTiming);
    cudaEventCreateWithFlags(&evJoin, cudaEventDisableTiming);

    cudaEventRecord(evFork, 0);
    cudaStreamWaitEvent(s2, evFork, 0);
    k_zero_cnt<<<ZC_BLKS, 256, 0, s2>>>();
    k_build<<<BUILD_BLKS, 256, 0, s2>>>(ei);
    cudaEventRecord(evJoin, s2);

    k_gemm_tc<IN_DIM, float><<<GEMM_BLKS, 256, SMEM_TC1>>>(
        x, W1l, W1r, b1, (__half*)py, (float*)pz);

    cudaStreamWaitEvent(0, evJoin, 0);
    k_gather<false><<<GATH_BLKS, 256>>>((const __half*)py, (const float*)pz,
                                        nullptr, nullptr, nullptr);
    k_gemm_tc<HID, __half><<<GEMM_BLKS, 256, SMEM_TC2>>>(
        (const __half*)ph, W2l, W2r, b2, (__half*)py2, (float*)pz2);
    k_gather<true><<<GATH_BLKS, 256>>>((const __half*)py2, (const float*)pz2,
                                       Wc, bc, out);

    cudaEventDestroy(evFork);
    cudaEventDestroy(evJoin);
    cudaStreamDestroy(s2);
}